// round 9
// baseline (speedup 1.0000x reference)
#include <cuda_runtime.h>
#include <math.h>

// Problem constants
#define BB 4
#define TT 2048
#define DD 512
#define HH 8
#define DH 64
#define LL 2
#define GG 64      // partial rows per batch (reduce & fused-gate emit blocks)
#define CHK 64     // gate-kernel blocks per batch (== GG)
#define EPSF 1e-5f

// Scratch (no device allocation allowed -> __device__ globals)
__device__ float g_part[BB][GG][DD];   // per-block partial sums of rstd*(x-mean)
__device__ float g_M[BB][HH][DD];      // folded per-head D-vectors
__device__ float g_S[BB][HH];          // sum_d M'
__device__ float g_bias[BB][HH];       // sum_d ln_b * M
__device__ float g_valid[2][BB];       // clipped valid counts: [0]=vid, [1]=aud
__device__ int   g_all[2][BB];         // all-masked flags

// ---------------------------------------------------------------------------
// Kernel 0: mask statistics (masks are int32)
// ---------------------------------------------------------------------------
__global__ void k_counts(const int* __restrict__ vid_kpm,
                         const int* __restrict__ aud_kpm) {
    int m = blockIdx.x >> 2;
    int b = blockIdx.x & 3;
    const int* kp = (m == 0 ? vid_kpm : aud_kpm) + (size_t)b * TT;
    int cnt = 0;
    for (int t = threadIdx.x; t < TT; t += 256) cnt += (kp[t] == 0);
    __shared__ int sh[256];
    sh[threadIdx.x] = cnt;
    __syncthreads();
    for (int s = 128; s > 0; s >>= 1) {
        if (threadIdx.x < s) sh[threadIdx.x] += sh[threadIdx.x + s];
        __syncthreads();
    }
    if (threadIdx.x == 0) {
        int c = sh[0];
        g_valid[m][b] = fmaxf((float)c, 1.0f);
        g_all[m][b] = (c == 0) ? 1 : 0;
    }
}

// ---------------------------------------------------------------------------
// Kernel A: masked sum over tokens of rstd*(x - mean) (initial aud pass only)
// grid (GG, BB), 256 threads; warp does 4 tokens in 2 groups of 2 (reg-slim);
// staged (atomic-free) fold.
// ---------------------------------------------------------------------------
__global__ void __launch_bounds__(256, 2)
k_reduce(const float* __restrict__ src, const int* __restrict__ kpm) {
    int b = blockIdx.y;
    int blk = blockIdx.x;
    int tid = threadIdx.x;
    int warp = tid >> 5, lane = tid & 31;

    __shared__ float stg[8 * DD];   // 16 KB staging: warp-major strips

    int t0 = blk * 32 + warp * 4;
    const float4* base = (const float4*)(src + ((size_t)b * TT + t0) * DD);

    float acc[16];
#pragma unroll
    for (int i = 0; i < 16; i++) acc[i] = 0.f;

#pragma unroll
    for (int g = 0; g < 2; g++) {
        float4 v[2][4];
        float s[2], sq[2];
#pragma unroll
        for (int t = 0; t < 2; t++) {
            s[t] = 0.f; sq[t] = 0.f;
#pragma unroll
            for (int k = 0; k < 4; k++) {
                float4 x = base[(g * 2 + t) * 128 + k * 32 + lane];
                v[t][k] = x;
                s[t]  += x.x + x.y + x.z + x.w;
                sq[t] += x.x * x.x + x.y * x.y + x.z * x.z + x.w * x.w;
            }
        }
#pragma unroll
        for (int off = 16; off; off >>= 1) {
#pragma unroll
            for (int t = 0; t < 2; t++) {
                s[t]  += __shfl_xor_sync(0xffffffffu, s[t], off);
                sq[t] += __shfl_xor_sync(0xffffffffu, sq[t], off);
            }
        }
#pragma unroll
        for (int t = 0; t < 2; t++) {
            if (kpm[(size_t)b * TT + t0 + g * 2 + t]) continue;
            float mean = s[t] * (1.f / DD);
            float var  = sq[t] * (1.f / DD) - mean * mean;
            float rstd = rsqrtf(var + EPSF);
            float sub  = rstd * mean;
#pragma unroll
            for (int k = 0; k < 4; k++) {
                acc[k * 4 + 0] += rstd * v[t][k].x - sub;
                acc[k * 4 + 1] += rstd * v[t][k].y - sub;
                acc[k * 4 + 2] += rstd * v[t][k].z - sub;
                acc[k * 4 + 3] += rstd * v[t][k].w - sub;
            }
        }
    }
    // stage per-warp partial rows (each warp covers all 512 dims)
#pragma unroll
    for (int k = 0; k < 4; k++)
        *(float4*)&stg[warp * DD + k * 128 + lane * 4] =
            make_float4(acc[k * 4], acc[k * 4 + 1], acc[k * 4 + 2], acc[k * 4 + 3]);
    __syncthreads();
    float r0 = 0.f, r1 = 0.f;
#pragma unroll
    for (int w = 0; w < 8; w++) {
        r0 += stg[w * DD + tid];
        r1 += stg[w * DD + tid + 256];
    }
    g_part[b][blk][tid]       = r0;
    g_part[b][blk][tid + 256] = r1;
}

// ---------------------------------------------------------------------------
// Kernel B: per (b,h): c = g*acc + cnt*b ; ksum = Wk_head @ c ;
//           M' = (scale/valid) * g ⊙ (Wq_head^T @ ksum) ; plus S, bias
// ---------------------------------------------------------------------------
__global__ void k_mid(const float* __restrict__ Wq, const float* __restrict__ Wk,
                      const float* __restrict__ lng, const float* __restrict__ lnb,
                      int srcm) {
    int b = blockIdx.x >> 3, h = blockIdx.x & 7;
    int tid = threadIdx.x;
    int warp = tid >> 5, lane = tid & 31;

    __shared__ float csh[DD];
    __shared__ float ksh[DH];
    __shared__ float rs[16], rb[16];

    float validf = g_valid[srcm][b];
    float cntf = g_all[srcm][b] ? 0.f : validf;

    float acc = 0.f;
#pragma unroll 8
    for (int g = 0; g < GG; g++) acc += g_part[b][g][tid];
    csh[tid] = lng[tid] * acc + cntf * lnb[tid];
    __syncthreads();

#pragma unroll
    for (int jj = 0; jj < 4; jj++) {
        int j = warp * 4 + jj;
        const float* wk = Wk + (size_t)(h * DH + j) * DD;
        float s = 0.f;
#pragma unroll
        for (int k = 0; k < 16; k++) { int d = lane + 32 * k; s += csh[d] * wk[d]; }
#pragma unroll
        for (int off = 16; off; off >>= 1) s += __shfl_xor_sync(0xffffffffu, s, off);
        if (lane == 0) ksh[j] = s;
    }
    __syncthreads();

    float m = 0.f;
#pragma unroll
    for (int j = 0; j < DH; j++) m += ksh[j] * Wq[(size_t)(h * DH + j) * DD + tid];
    m *= 0.125f / validf;
    float mp = m * lng[tid];
    g_M[b][h][tid] = mp;

    float sv = mp, bv = lnb[tid] * m;
#pragma unroll
    for (int off = 16; off; off >>= 1) {
        sv += __shfl_xor_sync(0xffffffffu, sv, off);
        bv += __shfl_xor_sync(0xffffffffu, bv, off);
    }
    if (lane == 0) { rs[warp] = sv; rb[warp] = bv; }
    __syncthreads();
    if (tid == 0) {
        float S = 0.f, Bv = 0.f;
        for (int w = 0; w < 16; w++) { S += rs[w]; Bv += rb[w]; }
        g_S[b][h] = S;
        g_bias[b][h] = Bv;
    }
}

// ---------------------------------------------------------------------------
// Kernel C (fused): warp does 4 tokens in 2 groups of 2 (register-slim so
//   2 blocks/SM -> single wave). Msh float4 loads feed 2 tokens each.
//   Butterfly reductions leave sums in all lanes -> lane-parallel MLP.
//   Emit path stages per-warp partials through Msh -- no atomics.
// grid (CHK, BB), 256 threads, 2 blocks/SM.
// ---------------------------------------------------------------------------
__global__ void __launch_bounds__(256, 2)
k_gate(const float* __restrict__ xin, float* xout,
       const float* __restrict__ W1, const float* __restrict__ b1,
       const float* __restrict__ W2, const float* __restrict__ b2,
       int srcm, const int* __restrict__ emit_kpm, int emit) {
    int b = blockIdx.y, blk = blockIdx.x;
    int tid = threadIdx.x;
    int warp = tid >> 5, lane = tid & 31;

    __shared__ float Msh[HH * DD];             // 16 KB; reused as emit staging
    __shared__ float Ssh[HH], Bsh[HH];
    __shared__ float W1sh[128], b1sh[16], W2sh[16];
    __shared__ float b2sh;
    __shared__ int allsh;

    {
        const float4* msrc = (const float4*)&g_M[b][0][0];
        float4* mdst = (float4*)&Msh[0];
#pragma unroll
        for (int i = 0; i < 4; i++) mdst[tid + i * 256] = msrc[tid + i * 256];
        if (tid < HH) { Ssh[tid] = g_S[b][tid]; Bsh[tid] = g_bias[b][tid]; }
        if (tid >= 32 && tid < 160) W1sh[tid - 32] = W1[tid - 32];
        if (tid >= 160 && tid < 176) b1sh[tid - 160] = b1[tid - 160];
        if (tid >= 176 && tid < 192) W2sh[tid - 176] = W2[tid - 176];
        if (tid == 192) b2sh = b2[0];
        if (tid == 193) allsh = g_all[srcm][b];
    }
    __syncthreads();

    int t0 = blk * 32 + warp * 4;              // 4 consecutive tokens per warp
    const float4* base = (const float4*)(xin + ((size_t)b * TT + t0) * DD);
    float4* obase = (float4*)(xout + ((size_t)b * TT + t0) * DD);
    const float4* M4 = (const float4*)&Msh[0];
    int eidx = lane & 15;

    float acc[16];
#pragma unroll
    for (int i = 0; i < 16; i++) acc[i] = 0.f;

#pragma unroll
    for (int g = 0; g < 2; g++) {
        // load 2 tokens
        float4 v[2][4];
        float s[2], sq[2];
#pragma unroll
        for (int t = 0; t < 2; t++) {
            s[t] = 0.f; sq[t] = 0.f;
#pragma unroll
            for (int k = 0; k < 4; k++) {
                float4 x = base[(g * 2 + t) * 128 + k * 32 + lane];
                v[t][k] = x;
                s[t]  += x.x + x.y + x.z + x.w;
                sq[t] += x.x * x.x + x.y * x.y + x.z * x.z + x.w * x.w;
            }
        }
        // dots: each Msh float4 feeds both tokens
        float dot[2][8];
#pragma unroll
        for (int t = 0; t < 2; t++)
#pragma unroll
            for (int h = 0; h < 8; h++) dot[t][h] = 0.f;
#pragma unroll
        for (int k = 0; k < 4; k++) {
#pragma unroll
            for (int h = 0; h < 8; h++) {
                float4 mv = M4[h * 128 + k * 32 + lane];
#pragma unroll
                for (int t = 0; t < 2; t++) {
                    dot[t][h] += v[t][k].x * mv.x + v[t][k].y * mv.y
                               + v[t][k].z * mv.z + v[t][k].w * mv.w;
                }
            }
        }
        // butterfly reductions (all lanes end with full sums)
#pragma unroll
        for (int off = 16; off; off >>= 1) {
#pragma unroll
            for (int t = 0; t < 2; t++) {
                s[t]  += __shfl_xor_sync(0xffffffffu, s[t], off);
                sq[t] += __shfl_xor_sync(0xffffffffu, sq[t], off);
#pragma unroll
                for (int h = 0; h < 8; h++)
                    dot[t][h] += __shfl_xor_sync(0xffffffffu, dot[t][h], off);
            }
        }

#pragma unroll
        for (int t = 0; t < 2; t++) {
            float mean = s[t] * (1.f / DD);
            float var  = sq[t] * (1.f / DD) - mean * mean;
            float rstd = rsqrtf(var + EPSF);
            float rel[8];
#pragma unroll
            for (int h = 0; h < 8; h++)
                rel[h] = rstd * (dot[t][h] - mean * Ssh[h]) + Bsh[h];
            // lane-parallel MLP: lane -> hidden unit (lane&15), units x2
            float a = b1sh[eidx];
#pragma unroll
            for (int h = 0; h < 8; h++) a += rel[h] * W1sh[eidx * 8 + h];
            float part = fmaxf(a, 0.f) * W2sh[eidx];
#pragma unroll
            for (int off = 16; off; off >>= 1)
                part += __shfl_xor_sync(0xffffffffu, part, off);
            float gacc = b2sh + 0.5f * part;
            float gate = 1.f / (1.f + expf(-gacc));
            if (allsh) gate = 0.f;
            float factor = 1.f + gate;

#pragma unroll
            for (int k = 0; k < 4; k++) {
                float4 o;
                o.x = v[t][k].x * factor; o.y = v[t][k].y * factor;
                o.z = v[t][k].z * factor; o.w = v[t][k].w * factor;
                obase[(g * 2 + t) * 128 + k * 32 + lane] = o;
            }
            if (emit && emit_kpm[(size_t)b * TT + t0 + g * 2 + t] == 0) {
                // LN partials of the output row (mean'=f*mean, var'=f^2*var)
                float rstd2 = rsqrtf(factor * factor * var + EPSF);
                float rf = rstd2 * factor;
                float sub2 = rf * mean;
#pragma unroll
                for (int k = 0; k < 4; k++) {
                    acc[k * 4 + 0] += rf * v[t][k].x - sub2;
                    acc[k * 4 + 1] += rf * v[t][k].y - sub2;
                    acc[k * 4 + 2] += rf * v[t][k].z - sub2;
                    acc[k * 4 + 3] += rf * v[t][k].w - sub2;
                }
            }
        }
    }

    if (emit) {
        __syncthreads();   // Msh reads done everywhere; reuse as staging
#pragma unroll
        for (int k = 0; k < 4; k++)
            *(float4*)&Msh[warp * DD + k * 128 + lane * 4] =
                make_float4(acc[k * 4], acc[k * 4 + 1], acc[k * 4 + 2], acc[k * 4 + 3]);
        __syncthreads();
        float r0 = 0.f, r1 = 0.f;
#pragma unroll
        for (int w = 0; w < 8; w++) {
            r0 += Msh[w * DD + tid];
            r1 += Msh[w * DD + tid + 256];
        }
        g_part[b][blk][tid]       = r0;
        g_part[b][blk][tid + 256] = r1;
    }
}

// ---------------------------------------------------------------------------
extern "C" void kernel_launch(void* const* d_in, const int* in_sizes, int n_in,
                              void* d_out, int out_size) {
    (void)in_sizes; (void)n_in; (void)out_size;
    const float* x_vid = (const float*)d_in[0];
    const float* x_aud = (const float*)d_in[1];
    const int* vid_kpm = (const int*)d_in[2];
    const int* aud_kpm = (const int*)d_in[3];
    const float* Wq_vid = (const float*)d_in[4];
    const float* Wk_aud = (const float*)d_in[5];
    const float* Wq_aud = (const float*)d_in[6];
    const float* Wk_vid = (const float*)d_in[7];
    const float* vgW1 = (const float*)d_in[8];
    const float* vgb1 = (const float*)d_in[9];
    const float* vgW2 = (const float*)d_in[10];
    const float* vgb2 = (const float*)d_in[11];
    const float* agW1 = (const float*)d_in[12];
    const float* agb1 = (const float*)d_in[13];
    const float* agW2 = (const float*)d_in[14];
    const float* agb2 = (const float*)d_in[15];
    const float* vid_g = (const float*)d_in[16];
    const float* vid_b = (const float*)d_in[17];
    const float* aud_g = (const float*)d_in[18];
    const float* aud_b = (const float*)d_in[19];

    const size_t N = (size_t)BB * TT * DD;
    float* out_vid = (float*)d_out;
    float* out_aud = out_vid + N;

    k_counts<<<8, 256>>>(vid_kpm, aud_kpm);

    // initial source reduce: LN-sum of x_aud under aud mask
    k_reduce<<<dim3(GG, BB), 256>>>(x_aud, aud_kpm);

    const float* cur_vid = x_vid;
    const float* cur_aud = x_aud;
    for (int l = 0; l < LL; l++) {
        size_t wofs = (size_t)l * DD * DD;
        // --- vid stage: source = aud (mask 1); gate vid; emit vid partials ---
        k_mid<<<BB * HH, 512>>>(Wq_vid + wofs, Wk_aud + wofs,
                                vid_g + (size_t)l * DD, vid_b + (size_t)l * DD, 1);
        k_gate<<<dim3(CHK, BB), 256>>>(cur_vid, out_vid,
                                       vgW1 + (size_t)l * 128, vgb1 + (size_t)l * 16,
                                       vgW2 + (size_t)l * 16, vgb2 + l, 1,
                                       vid_kpm, 1);
        cur_vid = out_vid;
        // --- aud stage: source = updated vid (mask 0); gate aud ---
        int emit_aud = (l < LL - 1) ? 1 : 0;
        k_mid<<<BB * HH, 512>>>(Wq_aud + wofs, Wk_vid + wofs,
                                aud_g + (size_t)l * DD, aud_b + (size_t)l * DD, 0);
        k_gate<<<dim3(CHK, BB), 256>>>(cur_aud, out_aud,
                                       agW1 + (size_t)l * 128, agb1 + (size_t)l * 16,
                                       agW2 + (size_t)l * 16, agb2 + l, 0,
                                       aud_kpm, emit_aud);
        cur_aud = out_aud;
    }
}

// round 10
// speedup vs baseline: 1.5923x; 1.5923x over previous
#include <cuda_runtime.h>
#include <math.h>

// Problem constants
#define BB 4
#define TT 2048
#define DD 512
#define HH 8
#define DH 64
#define LL 2
#define GG 64      // partial rows per batch (reduce & fused-gate emit blocks)
#define CHK 64     // gate-kernel blocks per batch (== GG)
#define EPSF 1e-5f

// Scratch (no device allocation allowed -> __device__ globals)
__device__ float g_part[BB][GG][DD];   // per-block partial sums of rstd*(x-mean)
__device__ float g_M[BB][HH][DD];      // folded per-head D-vectors
__device__ float g_S[BB][HH];          // sum_d M'
__device__ float g_bias[BB][HH];       // sum_d ln_b * M
__device__ float g_valid[2][BB];       // clipped valid counts: [0]=vid, [1]=aud
__device__ int   g_all[2][BB];         // all-masked flags

// ---------------------------------------------------------------------------
// Kernel 0: mask statistics (masks are int32)
// ---------------------------------------------------------------------------
__global__ void k_counts(const int* __restrict__ vid_kpm,
                         const int* __restrict__ aud_kpm) {
    int m = blockIdx.x >> 2;
    int b = blockIdx.x & 3;
    const int* kp = (m == 0 ? vid_kpm : aud_kpm) + (size_t)b * TT;
    int cnt = 0;
    for (int t = threadIdx.x; t < TT; t += 256) cnt += (kp[t] == 0);
    __shared__ int sh[256];
    sh[threadIdx.x] = cnt;
    __syncthreads();
    for (int s = 128; s > 0; s >>= 1) {
        if (threadIdx.x < s) sh[threadIdx.x] += sh[threadIdx.x + s];
        __syncthreads();
    }
    if (threadIdx.x == 0) {
        int c = sh[0];
        g_valid[m][b] = fmaxf((float)c, 1.0f);
        g_all[m][b] = (c == 0) ? 1 : 0;
    }
}

// ---------------------------------------------------------------------------
// Kernel A: masked sum over tokens of rstd*(x - mean) (initial aud pass only)
// grid (GG, BB), 256 threads; warp batches 4 tokens; staged (atomic-free) fold
// (proven R7 version)
// ---------------------------------------------------------------------------
__global__ void k_reduce(const float* __restrict__ src,
                         const int* __restrict__ kpm) {
    int b = blockIdx.y;
    int blk = blockIdx.x;
    int tid = threadIdx.x;
    int warp = tid >> 5, lane = tid & 31;

    __shared__ float stg[8 * DD];   // 16 KB staging: warp-major strips

    int t0 = blk * 32 + warp * 4;
    const float4* base = (const float4*)(src + ((size_t)b * TT + t0) * DD);

    float4 v[4][4];
    float s[4], sq[4];
#pragma unroll
    for (int t = 0; t < 4; t++) {
        s[t] = 0.f; sq[t] = 0.f;
#pragma unroll
        for (int k = 0; k < 4; k++) {
            float4 x = base[t * 128 + k * 32 + lane];
            v[t][k] = x;
            s[t]  += x.x + x.y + x.z + x.w;
            sq[t] += x.x * x.x + x.y * x.y + x.z * x.z + x.w * x.w;
        }
    }
#pragma unroll
    for (int off = 16; off; off >>= 1) {
#pragma unroll
        for (int t = 0; t < 4; t++) {
            s[t]  += __shfl_xor_sync(0xffffffffu, s[t], off);
            sq[t] += __shfl_xor_sync(0xffffffffu, sq[t], off);
        }
    }
    float acc[16];
#pragma unroll
    for (int i = 0; i < 16; i++) acc[i] = 0.f;
#pragma unroll
    for (int t = 0; t < 4; t++) {
        if (kpm[(size_t)b * TT + t0 + t]) continue;
        float mean = s[t] * (1.f / DD);
        float var  = sq[t] * (1.f / DD) - mean * mean;
        float rstd = rsqrtf(var + EPSF);
        float sub  = rstd * mean;
#pragma unroll
        for (int k = 0; k < 4; k++) {
            acc[k * 4 + 0] += rstd * v[t][k].x - sub;
            acc[k * 4 + 1] += rstd * v[t][k].y - sub;
            acc[k * 4 + 2] += rstd * v[t][k].z - sub;
            acc[k * 4 + 3] += rstd * v[t][k].w - sub;
        }
    }
#pragma unroll
    for (int k = 0; k < 4; k++)
        *(float4*)&stg[warp * DD + k * 128 + lane * 4] =
            make_float4(acc[k * 4], acc[k * 4 + 1], acc[k * 4 + 2], acc[k * 4 + 3]);
    __syncthreads();
    float r0 = 0.f, r1 = 0.f;
#pragma unroll
    for (int w = 0; w < 8; w++) {
        r0 += stg[w * DD + tid];
        r1 += stg[w * DD + tid + 256];
    }
    g_part[b][blk][tid]       = r0;
    g_part[b][blk][tid + 256] = r1;
}

// ---------------------------------------------------------------------------
// Kernel B: per (b,h): c = g*acc + cnt*b ; ksum = Wk_head @ c ;
//           M' = (scale/valid) * g ⊙ (Wq_head^T @ ksum) ; plus S, bias
// ---------------------------------------------------------------------------
__global__ void k_mid(const float* __restrict__ Wq, const float* __restrict__ Wk,
                      const float* __restrict__ lng, const float* __restrict__ lnb,
                      int srcm) {
    int b = blockIdx.x >> 3, h = blockIdx.x & 7;
    int tid = threadIdx.x;
    int warp = tid >> 5, lane = tid & 31;

    __shared__ float csh[DD];
    __shared__ float ksh[DH];
    __shared__ float rs[16], rb[16];

    float validf = g_valid[srcm][b];
    float cntf = g_all[srcm][b] ? 0.f : validf;

    float acc = 0.f;
#pragma unroll 8
    for (int g = 0; g < GG; g++) acc += g_part[b][g][tid];
    csh[tid] = lng[tid] * acc + cntf * lnb[tid];
    __syncthreads();

#pragma unroll
    for (int jj = 0; jj < 4; jj++) {
        int j = warp * 4 + jj;
        const float* wk = Wk + (size_t)(h * DH + j) * DD;
        float s = 0.f;
#pragma unroll
        for (int k = 0; k < 16; k++) { int d = lane + 32 * k; s += csh[d] * wk[d]; }
#pragma unroll
        for (int off = 16; off; off >>= 1) s += __shfl_xor_sync(0xffffffffu, s, off);
        if (lane == 0) ksh[j] = s;
    }
    __syncthreads();

    float m = 0.f;
#pragma unroll
    for (int j = 0; j < DH; j++) m += ksh[j] * Wq[(size_t)(h * DH + j) * DD + tid];
    m *= 0.125f / validf;
    float mp = m * lng[tid];
    g_M[b][h][tid] = mp;

    float sv = mp, bv = lnb[tid] * m;
#pragma unroll
    for (int off = 16; off; off >>= 1) {
        sv += __shfl_xor_sync(0xffffffffu, sv, off);
        bv += __shfl_xor_sync(0xffffffffu, bv, off);
    }
    if (lane == 0) { rs[warp] = sv; rb[warp] = bv; }
    __syncthreads();
    if (tid == 0) {
        float S = 0.f, Bv = 0.f;
        for (int w = 0; w < 16; w++) { S += rs[w]; Bv += rb[w]; }
        g_S[b][h] = S;
        g_bias[b][h] = Bv;
    }
}

// ---------------------------------------------------------------------------
// Kernel C (fused): warp batches 4 tokens (full ILP) but does NOT keep token
//   data in registers: x is loaded per k-chunk for stats+dots, then RE-READ
//   (L1-hot, warp-private rows) in the epilogue for output/emit. Peak regs
//   ~100 -> 2 blocks/SM with the R7 schedule. Butterfly reductions leave
//   sums in all lanes -> lane-parallel MLP. Atomic-free emit via Msh staging.
// grid (CHK, BB), 256 threads, 2 blocks/SM.
// ---------------------------------------------------------------------------
__global__ void __launch_bounds__(256, 2)
k_gate(const float* __restrict__ xin, float* xout,
       const float* __restrict__ W1, const float* __restrict__ b1,
       const float* __restrict__ W2, const float* __restrict__ b2,
       int srcm, const int* __restrict__ emit_kpm, int emit) {
    int b = blockIdx.y, blk = blockIdx.x;
    int tid = threadIdx.x;
    int warp = tid >> 5, lane = tid & 31;

    __shared__ float Msh[HH * DD];             // 16 KB; reused as emit staging
    __shared__ float Ssh[HH], Bsh[HH];
    __shared__ float W1sh[128], b1sh[16], W2sh[16];
    __shared__ float b2sh;
    __shared__ int allsh;

    {
        const float4* msrc = (const float4*)&g_M[b][0][0];
        float4* mdst = (float4*)&Msh[0];
#pragma unroll
        for (int i = 0; i < 4; i++) mdst[tid + i * 256] = msrc[tid + i * 256];
        if (tid < HH) { Ssh[tid] = g_S[b][tid]; Bsh[tid] = g_bias[b][tid]; }
        if (tid >= 32 && tid < 160) W1sh[tid - 32] = W1[tid - 32];
        if (tid >= 160 && tid < 176) b1sh[tid - 160] = b1[tid - 160];
        if (tid >= 176 && tid < 192) W2sh[tid - 176] = W2[tid - 176];
        if (tid == 192) b2sh = b2[0];
        if (tid == 193) allsh = g_all[srcm][b];
    }
    __syncthreads();

    int t0 = blk * 32 + warp * 4;              // 4 consecutive tokens per warp
    const float4* base = (const float4*)(xin + ((size_t)b * TT + t0) * DD);
    float4* obase = (float4*)(xout + ((size_t)b * TT + t0) * DD);
    const float4* M4 = (const float4*)&Msh[0];
    int eidx = lane & 15;

    // ---- phase 1: stats + dots, x not retained ----
    float s[4], sq[4], dot[4][8];
#pragma unroll
    for (int t = 0; t < 4; t++) {
        s[t] = 0.f; sq[t] = 0.f;
#pragma unroll
        for (int h = 0; h < 8; h++) dot[t][h] = 0.f;
    }
#pragma unroll
    for (int k = 0; k < 4; k++) {
        float4 xv[4];
#pragma unroll
        for (int t = 0; t < 4; t++) {
            xv[t] = base[t * 128 + k * 32 + lane];
            s[t]  += xv[t].x + xv[t].y + xv[t].z + xv[t].w;
            sq[t] += xv[t].x * xv[t].x + xv[t].y * xv[t].y
                   + xv[t].z * xv[t].z + xv[t].w * xv[t].w;
        }
#pragma unroll
        for (int h = 0; h < 8; h++) {
            float4 mv = M4[h * 128 + k * 32 + lane];
#pragma unroll
            for (int t = 0; t < 4; t++) {
                dot[t][h] += xv[t].x * mv.x + xv[t].y * mv.y
                           + xv[t].z * mv.z + xv[t].w * mv.w;
            }
        }
    }
    // ---- phase 2: butterfly reductions (all lanes get full sums) ----
#pragma unroll
    for (int off = 16; off; off >>= 1) {
#pragma unroll
        for (int t = 0; t < 4; t++) {
            s[t]  += __shfl_xor_sync(0xffffffffu, s[t], off);
            sq[t] += __shfl_xor_sync(0xffffffffu, sq[t], off);
#pragma unroll
            for (int h = 0; h < 8; h++)
                dot[t][h] += __shfl_xor_sync(0xffffffffu, dot[t][h], off);
        }
    }
    // ---- phase 3: per-token gate (lane-parallel MLP, 4 chains interleaved) ----
    float mean[4], var[4], part[4];
#pragma unroll
    for (int t = 0; t < 4; t++) {
        mean[t] = s[t] * (1.f / DD);
        var[t]  = sq[t] * (1.f / DD) - mean[t] * mean[t];
        float rstd = rsqrtf(var[t] + EPSF);
        float a = b1sh[eidx];
#pragma unroll
        for (int h = 0; h < 8; h++) {
            float rel = rstd * (dot[t][h] - mean[t] * Ssh[h]) + Bsh[h];
            a += rel * W1sh[eidx * 8 + h];
        }
        part[t] = fmaxf(a, 0.f) * W2sh[eidx];
    }
#pragma unroll
    for (int off = 16; off; off >>= 1)
#pragma unroll
        for (int t = 0; t < 4; t++)
            part[t] += __shfl_xor_sync(0xffffffffu, part[t], off);

    float factor[4], rf[4], sub2[4];
#pragma unroll
    for (int t = 0; t < 4; t++) {
        float gacc = b2sh + 0.5f * part[t];
        float gate = 1.f / (1.f + expf(-gacc));
        if (allsh) gate = 0.f;
        factor[t] = 1.f + gate;
        float rstd2 = rsqrtf(factor[t] * factor[t] * var[t] + EPSF);
        rf[t]   = rstd2 * factor[t];
        sub2[t] = rf[t] * mean[t];
    }

    // ---- phase 4: re-read x (L1-hot), write out, accumulate emit partials ----
    float acc[16];
#pragma unroll
    for (int i = 0; i < 16; i++) acc[i] = 0.f;
#pragma unroll
    for (int t = 0; t < 4; t++) {
        int keep = emit ? (emit_kpm[(size_t)b * TT + t0 + t] == 0) : 0;
#pragma unroll
        for (int k = 0; k < 4; k++) {
            float4 x = base[t * 128 + k * 32 + lane];
            float4 o;
            o.x = x.x * factor[t]; o.y = x.y * factor[t];
            o.z = x.z * factor[t]; o.w = x.w * factor[t];
            obase[t * 128 + k * 32 + lane] = o;
            if (keep) {
                acc[k * 4 + 0] += rf[t] * x.x - sub2[t];
                acc[k * 4 + 1] += rf[t] * x.y - sub2[t];
                acc[k * 4 + 2] += rf[t] * x.z - sub2[t];
                acc[k * 4 + 3] += rf[t] * x.w - sub2[t];
            }
        }
    }

    if (emit) {
        __syncthreads();   // Msh reads done everywhere; reuse as staging
#pragma unroll
        for (int k = 0; k < 4; k++)
            *(float4*)&Msh[warp * DD + k * 128 + lane * 4] =
                make_float4(acc[k * 4], acc[k * 4 + 1], acc[k * 4 + 2], acc[k * 4 + 3]);
        __syncthreads();
        float r0 = 0.f, r1 = 0.f;
#pragma unroll
        for (int w = 0; w < 8; w++) {
            r0 += Msh[w * DD + tid];
            r1 += Msh[w * DD + tid + 256];
        }
        g_part[b][blk][tid]       = r0;
        g_part[b][blk][tid + 256] = r1;
    }
}

// ---------------------------------------------------------------------------
extern "C" void kernel_launch(void* const* d_in, const int* in_sizes, int n_in,
                              void* d_out, int out_size) {
    (void)in_sizes; (void)n_in; (void)out_size;
    const float* x_vid = (const float*)d_in[0];
    const float* x_aud = (const float*)d_in[1];
    const int* vid_kpm = (const int*)d_in[2];
    const int* aud_kpm = (const int*)d_in[3];
    const float* Wq_vid = (const float*)d_in[4];
    const float* Wk_aud = (const float*)d_in[5];
    const float* Wq_aud = (const float*)d_in[6];
    const float* Wk_vid = (const float*)d_in[7];
    const float* vgW1 = (const float*)d_in[8];
    const float* vgb1 = (const float*)d_in[9];
    const float* vgW2 = (const float*)d_in[10];
    const float* vgb2 = (const float*)d_in[11];
    const float* agW1 = (const float*)d_in[12];
    const float* agb1 = (const float*)d_in[13];
    const float* agW2 = (const float*)d_in[14];
    const float* agb2 = (const float*)d_in[15];
    const float* vid_g = (const float*)d_in[16];
    const float* vid_b = (const float*)d_in[17];
    const float* aud_g = (const float*)d_in[18];
    const float* aud_b = (const float*)d_in[19];

    const size_t N = (size_t)BB * TT * DD;
    float* out_vid = (float*)d_out;
    float* out_aud = out_vid + N;

    k_counts<<<8, 256>>>(vid_kpm, aud_kpm);

    // initial source reduce: LN-sum of x_aud under aud mask
    k_reduce<<<dim3(GG, BB), 256>>>(x_aud, aud_kpm);

    const float* cur_vid = x_vid;
    const float* cur_aud = x_aud;
    for (int l = 0; l < LL; l++) {
        size_t wofs = (size_t)l * DD * DD;
        // --- vid stage: source = aud (mask 1); gate vid; emit vid partials ---
        k_mid<<<BB * HH, 512>>>(Wq_vid + wofs, Wk_aud + wofs,
                                vid_g + (size_t)l * DD, vid_b + (size_t)l * DD, 1);
        k_gate<<<dim3(CHK, BB), 256>>>(cur_vid, out_vid,
                                       vgW1 + (size_t)l * 128, vgb1 + (size_t)l * 16,
                                       vgW2 + (size_t)l * 16, vgb2 + l, 1,
                                       vid_kpm, 1);
        cur_vid = out_vid;
        // --- aud stage: source = updated vid (mask 0); gate aud ---
        int emit_aud = (l < LL - 1) ? 1 : 0;
        k_mid<<<BB * HH, 512>>>(Wq_aud + wofs, Wk_vid + wofs,
                                aud_g + (size_t)l * DD, aud_b + (size_t)l * DD, 0);
        k_gate<<<dim3(CHK, BB), 256>>>(cur_aud, out_aud,
                                       agW1 + (size_t)l * 128, agb1 + (size_t)l * 16,
                                       agW2 + (size_t)l * 16, agb2 + l, 0,
                                       aud_kpm, emit_aud);
        cur_aud = out_aud;
    }
}